// round 1
// baseline (speedup 1.0000x reference)
#include <cuda_runtime.h>
#include <cuda_bf16.h>

// LayerHypercube: out[b, f*1024+o] = sum_j x[b, o^(1<<j)] * w[f,j,o] + bias[f,o] + x[b,o]
// B=2048, F=16, O=IN=1024, BITS=10. fm[f,j,o] == o^(1<<j) (computed, not loaded).

#define BATCH   2048
#define INSZ    1024
#define OUTSZ   1024
#define NFM     16
#define NBITS   10

#define THREADS 128
#define OG      16              // o-groups (of 4) per block -> O_TILE = 64
#define OTILE   64
#define ROWS    16              // batch rows per block
#define OBLOCKS (OUTSZ / OTILE) // 16
#define BBLOCKS (BATCH / ROWS)  // 128

__global__ __launch_bounds__(THREADS)
void hypercube_kernel(const float* __restrict__ x,
                      const float* __restrict__ w,
                      const float* __restrict__ bias,
                      float* __restrict__ out)
{
    __shared__ float4 buf[INSZ / 4];   // one full x row, 4 KB

    const int tid  = threadIdx.x;
    const int og   = tid & (OG - 1);       // 0..15
    const int fp   = tid >> 4;             // 0..7
    const int obase = blockIdx.x * OTILE + og * 4;
    const int row0  = blockIdx.y * ROWS;

    const int f0 = fp;
    const int f1 = fp + 8;

    // Weights for this thread's (f0,f1) x 4 o-columns x 10 bits -> registers.
    float4 w0[NBITS], w1[NBITS];
#pragma unroll
    for (int j = 0; j < NBITS; j++) {
        w0[j] = *reinterpret_cast<const float4*>(w + ((f0 * NBITS + j) * OUTSZ + obase));
        w1[j] = *reinterpret_cast<const float4*>(w + ((f1 * NBITS + j) * OUTSZ + obase));
    }
    const float4 b0 = *reinterpret_cast<const float4*>(bias + f0 * OUTSZ + obase);
    const float4 b1 = *reinterpret_cast<const float4*>(bias + f1 * OUTSZ + obase);

    const int g = obase >> 2;  // this thread's own float4 group in the row

    // Prefetch first row (each thread covers groups tid and tid+128)
    const float4* xrow = reinterpret_cast<const float4*>(x + (size_t)row0 * INSZ);
    float4 xn0 = xrow[tid];
    float4 xn1 = xrow[tid + THREADS];

    for (int r = 0; r < ROWS; r++) {
        buf[tid]           = xn0;
        buf[tid + THREADS] = xn1;
        __syncthreads();

        if (r + 1 < ROWS) {
            const float4* xr = reinterpret_cast<const float4*>(
                x + (size_t)(row0 + r + 1) * INSZ);
            xn0 = xr[tid];
            xn1 = xr[tid + THREADS];
        }

        const float4 xo = buf[g];

        // acc = bias + tiled x
        float4 a0, a1;
        a0.x = b0.x + xo.x; a0.y = b0.y + xo.y; a0.z = b0.z + xo.z; a0.w = b0.w + xo.w;
        a1.x = b1.x + xo.x; a1.y = b1.y + xo.y; a1.z = b1.z + xo.z; a1.w = b1.w + xo.w;

        // j = 0: x[o^1] = swap within pairs -> (y, x, w, z)
        a0.x += w0[0].x * xo.y; a0.y += w0[0].y * xo.x;
        a0.z += w0[0].z * xo.w; a0.w += w0[0].w * xo.z;
        a1.x += w1[0].x * xo.y; a1.y += w1[0].y * xo.x;
        a1.z += w1[0].z * xo.w; a1.w += w1[0].w * xo.z;

        // j = 1: x[o^2] = swap halves -> (z, w, x, y)
        a0.x += w0[1].x * xo.z; a0.y += w0[1].y * xo.w;
        a0.z += w0[1].z * xo.x; a0.w += w0[1].w * xo.y;
        a1.x += w1[1].x * xo.z; a1.y += w1[1].y * xo.w;
        a1.z += w1[1].z * xo.x; a1.w += w1[1].w * xo.y;

        // j = 2..9: one aligned float4 gather per bit, shared between f0 and f1
#pragma unroll
        for (int j = 2; j < NBITS; j++) {
            const float4 gx = buf[g ^ (1 << (j - 2))];
            a0.x += w0[j].x * gx.x; a0.y += w0[j].y * gx.y;
            a0.z += w0[j].z * gx.z; a0.w += w0[j].w * gx.w;
            a1.x += w1[j].x * gx.x; a1.y += w1[j].y * gx.y;
            a1.z += w1[j].z * gx.z; a1.w += w1[j].w * gx.w;
        }

        const size_t b = (size_t)(row0 + r);
        float* outrow = out + b * (NFM * OUTSZ);
        *reinterpret_cast<float4*>(outrow + f0 * OUTSZ + obase) = a0;
        *reinterpret_cast<float4*>(outrow + f1 * OUTSZ + obase) = a1;

        __syncthreads();
    }
}

extern "C" void kernel_launch(void* const* d_in, const int* in_sizes, int n_in,
                              void* d_out, int out_size)
{
    const float* x    = (const float*)d_in[0];
    const float* w    = (const float*)d_in[1];
    const float* bias = (const float*)d_in[2];
    // d_in[3] = fm (int32) — values are o^(1<<j), computed inline instead.
    float* out = (float*)d_out;

    dim3 grid(OBLOCKS, BBLOCKS);
    hypercube_kernel<<<grid, THREADS>>>(x, w, bias, out);
}

// round 2
// speedup vs baseline: 1.5719x; 1.5719x over previous
#include <cuda_runtime.h>
#include <cuda_bf16.h>
#include <cstdint>

// LayerHypercube: out[b, f*1024+o] = sum_j x[b, o^(1<<j)] * w[f,j,o] + bias[f,o] + x[b,o]
// B=2048, F=16, O=IN=1024, BITS=10. fm[f,j,o] == o^(1<<j) (computed, not loaded).

#define BATCH   2048
#define INSZ    1024
#define OUTSZ   1024
#define NFM     16
#define NBITS   10

#define THREADS 128
#define OG      16              // o-groups (of 4) per block -> O_TILE = 64
#define OTILE   64
#define ROWS    16              // batch rows per block
#define OBLOCKS (OUTSZ / OTILE) // 16
#define BBLOCKS (BATCH / ROWS)  // 128
#define NBUF    3               // triple-buffered x rows

__device__ __forceinline__ void cp16(uint32_t dst_smem, const void* src_gmem) {
    asm volatile("cp.async.cg.shared.global [%0], [%1], 16;\n"
                 :: "r"(dst_smem), "l"(src_gmem));
}
__device__ __forceinline__ void cp_commit() {
    asm volatile("cp.async.commit_group;\n");
}
__device__ __forceinline__ void cp_wait1() {
    asm volatile("cp.async.wait_group 1;\n");
}

__global__ __launch_bounds__(THREADS, 4)
void hypercube_kernel(const float* __restrict__ x,
                      const float* __restrict__ w,
                      const float* __restrict__ bias,
                      float* __restrict__ out)
{
    __shared__ float4 buf[NBUF][INSZ / 4];   // 3 x 4KB x rows

    const int tid  = threadIdx.x;
    const int og   = tid & (OG - 1);       // 0..15
    const int fp   = tid >> 4;             // 0..7
    const int obase = blockIdx.x * OTILE + og * 4;
    const int row0  = blockIdx.y * ROWS;

    const int f0 = fp;
    const int f1 = fp + 8;

    // Weights for this thread's (f0,f1) x 4 o-columns x 10 bits -> registers.
    float4 w0[NBITS], w1[NBITS];
#pragma unroll
    for (int j = 0; j < NBITS; j++) {
        w0[j] = *reinterpret_cast<const float4*>(w + ((f0 * NBITS + j) * OUTSZ + obase));
        w1[j] = *reinterpret_cast<const float4*>(w + ((f1 * NBITS + j) * OUTSZ + obase));
    }
    const float4 b0 = *reinterpret_cast<const float4*>(bias + f0 * OUTSZ + obase);
    const float4 b1 = *reinterpret_cast<const float4*>(bias + f1 * OUTSZ + obase);

    const int g = obase >> 2;  // this thread's own float4 group in the row

    // smem byte addresses for this thread's two 16B staging slots in each buffer
    uint32_t sb[NBUF][2];
#pragma unroll
    for (int i = 0; i < NBUF; i++) {
        sb[i][0] = (uint32_t)__cvta_generic_to_shared(&buf[i][tid]);
        sb[i][1] = (uint32_t)__cvta_generic_to_shared(&buf[i][tid + THREADS]);
    }

    // Prologue: issue rows 0 and 1 into buffers 0 and 1.
    {
        const float4* xr0 = reinterpret_cast<const float4*>(x + (size_t)row0 * INSZ);
        cp16(sb[0][0], xr0 + tid);
        cp16(sb[0][1], xr0 + tid + THREADS);
        cp_commit();
        const float4* xr1 = reinterpret_cast<const float4*>(x + (size_t)(row0 + 1) * INSZ);
        cp16(sb[1][0], xr1 + tid);
        cp16(sb[1][1], xr1 + tid + THREADS);
        cp_commit();
    }

    int cur = 0;   // buffer holding row r
    for (int r = 0; r < ROWS; r++) {
        cp_wait1();            // row r landed (<=1 younger group pending)
        __syncthreads();       // also fences last iteration's reads of the issue target

        // Issue row r+2 into buffer (cur+2)%3 — that buffer was consumed at
        // iteration r-1 and the barrier above ordered those reads.
        int nxt = cur + 2; if (nxt >= NBUF) nxt -= NBUF;
        if (r + 2 < ROWS) {
            const float4* xr = reinterpret_cast<const float4*>(
                x + (size_t)(row0 + r + 2) * INSZ);
            cp16(sb[nxt][0], xr + tid);
            cp16(sb[nxt][1], xr + tid + THREADS);
        }
        cp_commit();           // always commit to keep group accounting uniform

        const float4* rowb = buf[cur];
        const float4 xo = rowb[g];

        // acc = bias + tiled x
        float4 a0, a1;
        a0.x = b0.x + xo.x; a0.y = b0.y + xo.y; a0.z = b0.z + xo.z; a0.w = b0.w + xo.w;
        a1.x = b1.x + xo.x; a1.y = b1.y + xo.y; a1.z = b1.z + xo.z; a1.w = b1.w + xo.w;

        // j = 0: x[o^1] -> (y, x, w, z)
        a0.x += w0[0].x * xo.y; a0.y += w0[0].y * xo.x;
        a0.z += w0[0].z * xo.w; a0.w += w0[0].w * xo.z;
        a1.x += w1[0].x * xo.y; a1.y += w1[0].y * xo.x;
        a1.z += w1[0].z * xo.w; a1.w += w1[0].w * xo.z;

        // j = 1: x[o^2] -> (z, w, x, y)
        a0.x += w0[1].x * xo.z; a0.y += w0[1].y * xo.w;
        a0.z += w0[1].z * xo.x; a0.w += w0[1].w * xo.y;
        a1.x += w1[1].x * xo.z; a1.y += w1[1].y * xo.w;
        a1.z += w1[1].z * xo.x; a1.w += w1[1].w * xo.y;

        // j = 2..9: one aligned float4 gather per bit, shared between f0 and f1
#pragma unroll
        for (int j = 2; j < NBITS; j++) {
            const float4 gx = rowb[g ^ (1 << (j - 2))];
            a0.x += w0[j].x * gx.x; a0.y += w0[j].y * gx.y;
            a0.z += w0[j].z * gx.z; a0.w += w0[j].w * gx.w;
            a1.x += w1[j].x * gx.x; a1.y += w1[j].y * gx.y;
            a1.z += w1[j].z * gx.z; a1.w += w1[j].w * gx.w;
        }

        float* outrow = out + (size_t)(row0 + r) * (NFM * OUTSZ);
        __stcs(reinterpret_cast<float4*>(outrow + f0 * OUTSZ + obase), a0);
        __stcs(reinterpret_cast<float4*>(outrow + f1 * OUTSZ + obase), a1);

        cur = cur + 1; if (cur >= NBUF) cur -= NBUF;
    }
}

extern "C" void kernel_launch(void* const* d_in, const int* in_sizes, int n_in,
                              void* d_out, int out_size)
{
    const float* x    = (const float*)d_in[0];
    const float* w    = (const float*)d_in[1];
    const float* bias = (const float*)d_in[2];
    // d_in[3] = fm (int32) — values are o^(1<<j), computed inline instead.
    float* out = (float*)d_out;

    dim3 grid(OBLOCKS, BBLOCKS);
    hypercube_kernel<<<grid, THREADS>>>(x, w, bias, out);
}

// round 3
// speedup vs baseline: 1.7527x; 1.1150x over previous
#include <cuda_runtime.h>
#include <cuda_bf16.h>
#include <cstdint>

// LayerHypercube: out[b, f*1024+o] = sum_j x[b, o^(1<<j)] * w[f,j,o] + bias[f,o] + x[b,o]
// B=2048, F=16, O=IN=1024, BITS=10. fm[f,j,o] == o^(1<<j) (computed, not loaded).

#define BATCH   2048
#define INSZ    1024
#define OUTSZ   1024
#define NFM     16
#define NBITS   10

#define THREADS 128
#define OG      16              // o-groups (of 4) per block -> O_TILE = 64
#define OTILE   64
#define ROWS    32              // batch rows per block (16 pairs)
#define PAIRS   (ROWS / 2)
#define OBLOCKS (OUTSZ / OTILE) // 16
#define BBLOCKS (BATCH / ROWS)  // 64
#define NBUF    3               // triple-buffered row PAIRS

__device__ __forceinline__ void cp16(uint32_t dst_smem, const void* src_gmem) {
    asm volatile("cp.async.cg.shared.global [%0], [%1], 16;\n"
                 :: "r"(dst_smem), "l"(src_gmem));
}
__device__ __forceinline__ void cp_commit() {
    asm volatile("cp.async.commit_group;\n");
}
__device__ __forceinline__ void cp_wait1() {
    asm volatile("cp.async.wait_group 1;\n");
}

__global__ __launch_bounds__(THREADS, 3)
void hypercube_kernel(const float* __restrict__ x,
                      const float* __restrict__ w,
                      const float* __restrict__ bias,
                      float* __restrict__ out)
{
    __shared__ float4 buf[NBUF][2][INSZ / 4];   // 3 buffers x 2 rows x 4KB

    const int tid  = threadIdx.x;
    const int og   = tid & (OG - 1);       // 0..15
    const int fp   = tid >> 4;             // 0..7
    const int obase = blockIdx.x * OTILE + og * 4;
    const int row0  = blockIdx.y * ROWS;

    const int f0 = fp;
    const int f1 = fp + 8;

    // Weights for this thread's (f0,f1) x 4 o-columns x 10 bits -> registers.
    float4 w0[NBITS], w1[NBITS];
#pragma unroll
    for (int j = 0; j < NBITS; j++) {
        w0[j] = *reinterpret_cast<const float4*>(w + ((f0 * NBITS + j) * OUTSZ + obase));
        w1[j] = *reinterpret_cast<const float4*>(w + ((f1 * NBITS + j) * OUTSZ + obase));
    }
    const float4 b0 = *reinterpret_cast<const float4*>(bias + f0 * OUTSZ + obase);
    const float4 b1 = *reinterpret_cast<const float4*>(bias + f1 * OUTSZ + obase);

    const int g = obase >> 2;  // this thread's own float4 group in the row

    // Issue both rows of a pair into buffer i.
    auto issue_pair = [&](int i, int pair) {
        const float4* xr0 = reinterpret_cast<const float4*>(
            x + (size_t)(row0 + 2 * pair) * INSZ);
        const float4* xr1 = reinterpret_cast<const float4*>(
            x + (size_t)(row0 + 2 * pair + 1) * INSZ);
        cp16((uint32_t)__cvta_generic_to_shared(&buf[i][0][tid]),           xr0 + tid);
        cp16((uint32_t)__cvta_generic_to_shared(&buf[i][0][tid + THREADS]), xr0 + tid + THREADS);
        cp16((uint32_t)__cvta_generic_to_shared(&buf[i][1][tid]),           xr1 + tid);
        cp16((uint32_t)__cvta_generic_to_shared(&buf[i][1][tid + THREADS]), xr1 + tid + THREADS);
    };

    // Prologue: pairs 0 and 1 into buffers 0 and 1.
    issue_pair(0, 0); cp_commit();
    issue_pair(1, 1); cp_commit();

    int cur = 0;
    for (int s = 0; s < PAIRS; s++) {
        cp_wait1();            // pair s landed
        __syncthreads();       // fences prior reads of the buffer we refill below

        int nxt = cur + 2; if (nxt >= NBUF) nxt -= NBUF;
        if (s + 2 < PAIRS) issue_pair(nxt, s + 2);
        cp_commit();           // uniform group accounting

        const float4* rb0 = buf[cur][0];
        const float4* rb1 = buf[cur][1];
        const float4 p = rb0[g];
        const float4 q = rb1[g];

        // acc = bias + tiled x   (row A: a*, row B: c*)
        float4 a0, a1, c0, c1;
        a0.x = b0.x + p.x; a0.y = b0.y + p.y; a0.z = b0.z + p.z; a0.w = b0.w + p.w;
        a1.x = b1.x + p.x; a1.y = b1.y + p.y; a1.z = b1.z + p.z; a1.w = b1.w + p.w;
        c0.x = b0.x + q.x; c0.y = b0.y + q.y; c0.z = b0.z + q.z; c0.w = b0.w + q.w;
        c1.x = b1.x + q.x; c1.y = b1.y + q.y; c1.z = b1.z + q.z; c1.w = b1.w + q.w;

        // j = 0: x[o^1] -> (y, x, w, z)
        a0.x += w0[0].x * p.y; a0.y += w0[0].y * p.x; a0.z += w0[0].z * p.w; a0.w += w0[0].w * p.z;
        a1.x += w1[0].x * p.y; a1.y += w1[0].y * p.x; a1.z += w1[0].z * p.w; a1.w += w1[0].w * p.z;
        c0.x += w0[0].x * q.y; c0.y += w0[0].y * q.x; c0.z += w0[0].z * q.w; c0.w += w0[0].w * q.z;
        c1.x += w1[0].x * q.y; c1.y += w1[0].y * q.x; c1.z += w1[0].z * q.w; c1.w += w1[0].w * q.z;

        // j = 1: x[o^2] -> (z, w, x, y)
        a0.x += w0[1].x * p.z; a0.y += w0[1].y * p.w; a0.z += w0[1].z * p.x; a0.w += w0[1].w * p.y;
        a1.x += w1[1].x * p.z; a1.y += w1[1].y * p.w; a1.z += w1[1].z * p.x; a1.w += w1[1].w * p.y;
        c0.x += w0[1].x * q.z; c0.y += w0[1].y * q.w; c0.z += w0[1].z * q.x; c0.w += w0[1].w * q.y;
        c1.x += w1[1].x * q.z; c1.y += w1[1].y * q.w; c1.z += w1[1].z * q.x; c1.w += w1[1].w * q.y;

        // j = 2..9: one aligned float4 gather per bit per row, shared across f0/f1
#pragma unroll
        for (int j = 2; j < NBITS; j++) {
            const int gg = g ^ (1 << (j - 2));
            const float4 u = rb0[gg];
            const float4 v = rb1[gg];
            a0.x += w0[j].x * u.x; a0.y += w0[j].y * u.y; a0.z += w0[j].z * u.z; a0.w += w0[j].w * u.w;
            a1.x += w1[j].x * u.x; a1.y += w1[j].y * u.y; a1.z += w1[j].z * u.z; a1.w += w1[j].w * u.w;
            c0.x += w0[j].x * v.x; c0.y += w0[j].y * v.y; c0.z += w0[j].z * v.z; c0.w += w0[j].w * v.w;
            c1.x += w1[j].x * v.x; c1.y += w1[j].y * v.y; c1.z += w1[j].z * v.z; c1.w += w1[j].w * v.w;
        }

        float* outA = out + (size_t)(row0 + 2 * s)     * (NFM * OUTSZ);
        float* outB = out + (size_t)(row0 + 2 * s + 1) * (NFM * OUTSZ);
        __stcs(reinterpret_cast<float4*>(outA + f0 * OUTSZ + obase), a0);
        __stcs(reinterpret_cast<float4*>(outA + f1 * OUTSZ + obase), a1);
        __stcs(reinterpret_cast<float4*>(outB + f0 * OUTSZ + obase), c0);
        __stcs(reinterpret_cast<float4*>(outB + f1 * OUTSZ + obase), c1);

        cur = cur + 1; if (cur >= NBUF) cur -= NBUF;
    }
}

extern "C" void kernel_launch(void* const* d_in, const int* in_sizes, int n_in,
                              void* d_out, int out_size)
{
    const float* x    = (const float*)d_in[0];
    const float* w    = (const float*)d_in[1];
    const float* bias = (const float*)d_in[2];
    // d_in[3] = fm (int32) — values are o^(1<<j), computed inline instead.
    float* out = (float*)d_out;

    dim3 grid(OBLOCKS, BBLOCKS);
    hypercube_kernel<<<grid, THREADS>>>(x, w, bias, out);
}

// round 4
// speedup vs baseline: 1.8464x; 1.0534x over previous
#include <cuda_runtime.h>
#include <cuda_bf16.h>
#include <cstdint>

// LayerHypercube: out[b, f*1024+o] = sum_j x[b, o^(1<<j)] * w[f,j,o] + bias[f,o] + x[b,o]
// B=2048, F=16, O=IN=1024, BITS=10. fm[f,j,o] == o^(1<<j) (computed, not loaded).

#define BATCH   2048
#define INSZ    1024
#define OUTSZ   1024
#define NFM     16
#define NBITS   10

#define THREADS 128
#define OG      16              // o-groups (of 4) per block -> O_TILE = 64
#define OTILE   64
#define ROWS    32              // batch rows per block (16 pairs)
#define PAIRS   (ROWS / 2)
#define OBLOCKS (OUTSZ / OTILE) // 16
#define BBLOCKS (BATCH / ROWS)  // 64
#define NBUF    3               // triple-buffered row PAIRS (8KB each)

__device__ __forceinline__ void cp16(uint32_t dst_smem, const void* src_gmem) {
    asm volatile("cp.async.cg.shared.global [%0], [%1], 16;\n"
                 :: "r"(dst_smem), "l"(src_gmem));
}
__device__ __forceinline__ void cp_commit() {
    asm volatile("cp.async.commit_group;\n");
}
__device__ __forceinline__ void cp_wait1() {
    asm volatile("cp.async.wait_group 1;\n");
}

__global__ __launch_bounds__(THREADS, 4)
void hypercube_kernel(const float* __restrict__ x,
                      const float* __restrict__ w,
                      const float* __restrict__ bias,
                      float* __restrict__ out)
{
    __shared__ float4 buf[NBUF][2][INSZ / 4];   // 3 buffers x 2 rows x 4KB

    const int tid  = threadIdx.x;
    const int og   = tid & (OG - 1);       // 0..15
    const int fp   = tid >> 4;             // 0..7
    const int obase = blockIdx.x * OTILE + og * 4;
    const int row0  = blockIdx.y * ROWS;

    // Weights for (fp, fp+8) x 4 o-columns x 10 bits -> registers (80 regs).
    float4 w0[NBITS], w1[NBITS];
#pragma unroll
    for (int j = 0; j < NBITS; j++) {
        w0[j] = *reinterpret_cast<const float4*>(w + ((fp       * NBITS + j) * OUTSZ + obase));
        w1[j] = *reinterpret_cast<const float4*>(w + (((fp + 8) * NBITS + j) * OUTSZ + obase));
    }
    const float4 b0 = *reinterpret_cast<const float4*>(bias + fp       * OUTSZ + obase);
    const float4 b1 = *reinterpret_cast<const float4*>(bias + (fp + 8) * OUTSZ + obase);

    const int g = obase >> 2;  // this thread's own float4 group index in a row

    // One smem byte base; all 12 cp.async destinations are constant offsets.
    // buffer i at +i*8192, row r at +r*4096, slot1 at +2048.
    const uint32_t sb0 =
        (uint32_t)__cvta_generic_to_shared(&buf[0][0][tid]);

    // One gmem source pointer per pair; consecutive rows contiguous, so src
    // offsets {0,2048,4096,6144} mirror dst offsets.
    const char* xsrc = reinterpret_cast<const char*>(x + (size_t)row0 * INSZ) + tid * 16;

    // Prologue: pairs 0 and 1 into buffers 0 and 1.
#pragma unroll
    for (int i = 0; i < 2; i++) {
        const char* s = xsrc + i * 8192;
        uint32_t d = sb0 + i * 8192;
        cp16(d,        s);
        cp16(d + 2048, s + 2048);
        cp16(d + 4096, s + 4096);
        cp16(d + 6144, s + 6144);
        cp_commit();
    }

    // Output pointer: rowA/f0 element; f1 = +8192 floats, rowB = +16384 floats
    // (constant immediates in SASS). Advance by 2 rows per iteration.
    float* op = out + (size_t)row0 * (NFM * OUTSZ) + fp * OUTSZ + obase;

    int cur = 0;
    for (int s = 0; s < PAIRS; s++) {
        cp_wait1();            // pair s landed (own thread's copies)
        __syncthreads();       // visibility of all threads' copies + fences reads of refill target

        int nxt = cur + 2; if (nxt >= NBUF) nxt -= NBUF;
        if (s + 2 < PAIRS) {
            const char* src = xsrc + (size_t)(s + 2) * 8192;
            uint32_t d = sb0 + nxt * 8192;
            cp16(d,        src);
            cp16(d + 2048, src + 2048);
            cp16(d + 4096, src + 4096);
            cp16(d + 6144, src + 6144);
        }
        cp_commit();           // uniform group accounting

        const float4* rb0 = buf[cur][0];
        const float4* rb1 = buf[cur][1];
        const float4 p = rb0[g];
        const float4 q = rb1[g];

        // acc = bias + tiled x   (row A: a*, row B: c*)
        float4 a0, a1, c0, c1;
        a0.x = b0.x + p.x; a0.y = b0.y + p.y; a0.z = b0.z + p.z; a0.w = b0.w + p.w;
        a1.x = b1.x + p.x; a1.y = b1.y + p.y; a1.z = b1.z + p.z; a1.w = b1.w + p.w;
        c0.x = b0.x + q.x; c0.y = b0.y + q.y; c0.z = b0.z + q.z; c0.w = b0.w + q.w;
        c1.x = b1.x + q.x; c1.y = b1.y + q.y; c1.z = b1.z + q.z; c1.w = b1.w + q.w;

        // j = 0: x[o^1] -> (y, x, w, z)  (in-register permutation)
        a0.x += w0[0].x * p.y; a0.y += w0[0].y * p.x; a0.z += w0[0].z * p.w; a0.w += w0[0].w * p.z;
        a1.x += w1[0].x * p.y; a1.y += w1[0].y * p.x; a1.z += w1[0].z * p.w; a1.w += w1[0].w * p.z;
        c0.x += w0[0].x * q.y; c0.y += w0[0].y * q.x; c0.z += w0[0].z * q.w; c0.w += w0[0].w * q.z;
        c1.x += w1[0].x * q.y; c1.y += w1[0].y * q.x; c1.z += w1[0].z * q.w; c1.w += w1[0].w * q.z;

        // j = 1: x[o^2] -> (z, w, x, y)
        a0.x += w0[1].x * p.z; a0.y += w0[1].y * p.w; a0.z += w0[1].z * p.x; a0.w += w0[1].w * p.y;
        a1.x += w1[1].x * p.z; a1.y += w1[1].y * p.w; a1.z += w1[1].z * p.x; a1.w += w1[1].w * p.y;
        c0.x += w0[1].x * q.z; c0.y += w0[1].y * q.w; c0.z += w0[1].z * q.x; c0.w += w0[1].w * q.y;
        c1.x += w1[1].x * q.z; c1.y += w1[1].y * q.w; c1.z += w1[1].z * q.x; c1.w += w1[1].w * q.y;

        // j = 2..9: one aligned float4 gather per bit per row, shared across f0/f1
#pragma unroll
        for (int j = 2; j < NBITS; j++) {
            const int gg = g ^ (1 << (j - 2));
            const float4 u = rb0[gg];
            const float4 v = rb1[gg];
            a0.x += w0[j].x * u.x; a0.y += w0[j].y * u.y; a0.z += w0[j].z * u.z; a0.w += w0[j].w * u.w;
            a1.x += w1[j].x * u.x; a1.y += w1[j].y * u.y; a1.z += w1[j].z * u.z; a1.w += w1[j].w * u.w;
            c0.x += w0[j].x * v.x; c0.y += w0[j].y * v.y; c0.z += w0[j].z * v.z; c0.w += w0[j].w * v.w;
            c1.x += w1[j].x * v.x; c1.y += w1[j].y * v.y; c1.z += w1[j].z * v.z; c1.w += w1[j].w * v.w;
        }

        __stcs(reinterpret_cast<float4*>(op),                 a0);
        __stcs(reinterpret_cast<float4*>(op + 8 * OUTSZ),     a1);   // f1
        __stcs(reinterpret_cast<float4*>(op + NFM * OUTSZ),           c0);   // row B
        __stcs(reinterpret_cast<float4*>(op + NFM * OUTSZ + 8 * OUTSZ), c1);

        op += 2 * NFM * OUTSZ;
        cur = cur + 1; if (cur >= NBUF) cur -= NBUF;
    }
}

extern "C" void kernel_launch(void* const* d_in, const int* in_sizes, int n_in,
                              void* d_out, int out_size)
{
    const float* x    = (const float*)d_in[0];
    const float* w    = (const float*)d_in[1];
    const float* bias = (const float*)d_in[2];
    // d_in[3] = fm (int32) — values are o^(1<<j), computed inline instead.
    float* out = (float*)d_out;

    dim3 grid(OBLOCKS, BBLOCKS);
    hypercube_kernel<<<grid, THREADS>>>(x, w, bias, out);
}